// round 4
// baseline (speedup 1.0000x reference)
#include <cuda_runtime.h>

#define N_NODES 8192
#define E_EDGES 262144
#define IN_DIM  512
#define HID_DIM 256
#define Z_DIM   64

typedef unsigned long long ull;

// Scratch (device globals: allocation-free)
__device__ float g_h0[N_NODES * HID_DIM];   // x @ W1
__device__ float g_h [N_NODES * HID_DIM];   // relu(spmm(h0))
__device__ float g_p [N_NODES * Z_DIM];     // h @ W2
__device__ int   g_rowptr[N_NODES + 1];

// ---------------------------------------------------------------------------
// Packed f32x2 helpers
// ---------------------------------------------------------------------------
__device__ __forceinline__ ull pack2(float x, float y) {
    ull r; asm("mov.b64 %0, {%1, %2};" : "=l"(r) : "f"(x), "f"(y)); return r;
}
__device__ __forceinline__ ull dup2(float x) { return pack2(x, x); }
__device__ __forceinline__ ull fma2(ull a, ull b, ull c) {
    ull d; asm("fma.rn.f32x2 %0, %1, %2, %3;" : "=l"(d) : "l"(a), "l"(b), "l"(c));
    return d;
}
__device__ __forceinline__ float2 unpack2(ull v) {
    float2 f; asm("mov.b64 {%0, %1}, %2;" : "=f"(f.x), "=f"(f.y) : "l"(v)); return f;
}

// ---------------------------------------------------------------------------
// CSR row pointer from sorted edge_row
// ---------------------------------------------------------------------------
__global__ void rowptr_kernel(const int* __restrict__ er) {
    int i = blockIdx.x * blockDim.x + threadIdx.x;
    if (i > N_NODES) return;
    int lo = 0, hi = E_EDGES;
    while (lo < hi) {
        int mid = (lo + hi) >> 1;
        if (er[mid] < i) lo = mid + 1; else hi = mid;
    }
    g_rowptr[i] = lo;
}

// ---------------------------------------------------------------------------
// Tiled fp32 GEMM, register-prefetch double buffering. TM=TN=4, f32x2 inner.
// ---------------------------------------------------------------------------
template<int BM, int BN, int BK, int NT>
__global__ __launch_bounds__(NT) void sgemm_nn(
    const float* __restrict__ A, const float* __restrict__ B,
    float* __restrict__ C, int M, int K, int N)
{
    __shared__ float As[BK][BM + 4];
    __shared__ float Bs[BK][BN];
    const int LA = BM * BK / NT;
    const int LB = BK * BN / NT;
    const int tid = threadIdx.x;
    const int tx = tid % (BN / 4);
    const int ty = tid / (BN / 4);
    const int mbase = blockIdx.y * BM;
    const int nbase = blockIdx.x * BN;

    ull acc[4][2] = {};
    float apf[LA], bpf[LB];

    #pragma unroll
    for (int u = 0; u < LA; ++u) {
        int idx = tid + u * NT; int m = idx / BK, k = idx % BK;
        apf[u] = A[(size_t)(mbase + m) * K + k];
    }
    #pragma unroll
    for (int u = 0; u < LB; ++u) {
        int idx = tid + u * NT; int k = idx / BN, n = idx % BN;
        bpf[u] = B[(size_t)k * N + nbase + n];
    }

    for (int kk = 0; kk < K; kk += BK) {
        #pragma unroll
        for (int u = 0; u < LA; ++u) {
            int idx = tid + u * NT; int m = idx / BK, k = idx % BK;
            As[k][m] = apf[u];
        }
        #pragma unroll
        for (int u = 0; u < LB; ++u) {
            int idx = tid + u * NT; int k = idx / BN, n = idx % BN;
            Bs[k][n] = bpf[u];
        }
        __syncthreads();

        if (kk + BK < K) {
            #pragma unroll
            for (int u = 0; u < LA; ++u) {
                int idx = tid + u * NT; int m = idx / BK, k = idx % BK;
                apf[u] = A[(size_t)(mbase + m) * K + kk + BK + k];
            }
            #pragma unroll
            for (int u = 0; u < LB; ++u) {
                int idx = tid + u * NT; int k = idx / BN, n = idx % BN;
                bpf[u] = B[(size_t)(kk + BK + k) * N + nbase + n];
            }
        }

        #pragma unroll
        for (int k = 0; k < BK; ++k) {
            float4 a4 = *(const float4*)&As[k][ty * 4];
            float4 b4 = *(const float4*)&Bs[k][tx * 4];
            ull b2[2] = { pack2(b4.x, b4.y), pack2(b4.z, b4.w) };
            float a[4] = { a4.x, a4.y, a4.z, a4.w };
            #pragma unroll
            for (int i = 0; i < 4; ++i) {
                ull ad = dup2(a[i]);
                acc[i][0] = fma2(ad, b2[0], acc[i][0]);
                acc[i][1] = fma2(ad, b2[1], acc[i][1]);
            }
        }
        __syncthreads();
    }

    #pragma unroll
    for (int i = 0; i < 4; ++i) {
        float2 c0 = unpack2(acc[i][0]);
        float2 c1 = unpack2(acc[i][1]);
        size_t off = (size_t)(mbase + ty * 4 + i) * N + nbase + tx * 4;
        *(float4*)&C[off] = make_float4(c0.x, c0.y, c1.x, c1.y);
    }
}

// ---------------------------------------------------------------------------
// SpMM, float4 lanes
// ---------------------------------------------------------------------------
template<int D, bool RELU>
__global__ void spmm_kernel(const float* __restrict__ hin,
                            const int*   __restrict__ col,
                            const float* __restrict__ wgt,
                            float* __restrict__ hout)
{
    int row = blockIdx.x * blockDim.y + threadIdx.y;
    int d4 = threadIdx.x * 4;
    int s = g_rowptr[row];
    int e = g_rowptr[row + 1];
    float ax = 0.f, ay = 0.f, az = 0.f, aw = 0.f;
    int i = s;
    for (; i + 4 <= e; i += 4) {
        int   c0 = col[i+0], c1 = col[i+1], c2 = col[i+2], c3 = col[i+3];
        float w0 = wgt[i+0], w1 = wgt[i+1], w2 = wgt[i+2], w3 = wgt[i+3];
        float4 v0 = *(const float4*)&hin[(size_t)c0 * D + d4];
        float4 v1 = *(const float4*)&hin[(size_t)c1 * D + d4];
        float4 v2 = *(const float4*)&hin[(size_t)c2 * D + d4];
        float4 v3 = *(const float4*)&hin[(size_t)c3 * D + d4];
        ax += w0*v0.x + w1*v1.x + w2*v2.x + w3*v3.x;
        ay += w0*v0.y + w1*v1.y + w2*v2.y + w3*v3.y;
        az += w0*v0.z + w1*v1.z + w2*v2.z + w3*v3.z;
        aw += w0*v0.w + w1*v1.w + w2*v2.w + w3*v3.w;
    }
    for (; i < e; ++i) {
        float w = wgt[i];
        float4 v = *(const float4*)&hin[(size_t)col[i] * D + d4];
        ax += w*v.x; ay += w*v.y; az += w*v.z; aw += w*v.w;
    }
    if (RELU) {
        ax = fmaxf(ax, 0.f); ay = fmaxf(ay, 0.f);
        az = fmaxf(az, 0.f); aw = fmaxf(aw, 0.f);
    }
    *(float4*)&hout[(size_t)row * D + d4] = make_float4(ax, ay, az, aw);
}

// ---------------------------------------------------------------------------
// recon = Z @ Z^T, symmetric lower-triangle tiles, zero-MOV f32x2 mainloop.
// Spill-free: unroll 2, epilogue streams 8 floats at a time (never 64 live).
// ---------------------------------------------------------------------------
#define ZT   128
#define AD_S 264   // 256 + 8 pad (16B-aligned rows)
#define BP_S 136   // 128 + 8 pad
#define ZLD  132   // mirror-bounce stride

__global__ __launch_bounds__(256, 2) void zzt_sym_kernel(
    const float* __restrict__ Z, float* __restrict__ C)
{
    extern __shared__ float sm[];
    float* Ad = sm;                        // 64 * 264 floats = 67584 B
    float* Bp = sm + Z_DIM * AD_S;         // 64 * 136 floats = 34816 B

    const int l = blockIdx.x;
    int by = (int)((sqrtf(8.0f * (float)l + 1.0f) - 1.0f) * 0.5f);
    while ((by + 1) * (by + 2) / 2 <= l) ++by;
    while (by * (by + 1) / 2 > l) --by;
    const int bx = l - by * (by + 1) / 2;

    const int tid = threadIdx.x;
    const int tx = tid & 15;
    const int ty = tid >> 4;
    const int rbase = by * ZT;
    const int cbase = bx * ZT;

    // stage: A duplicated, B transposed
    const int k4 = tx * 4;
    for (int rr = ty; rr < ZT; rr += 16) {
        float4 va = *(const float4*)&Z[(size_t)(rbase + rr) * Z_DIM + k4];
        *(ull*)&Ad[(k4+0)*AD_S + 2*rr] = dup2(va.x);
        *(ull*)&Ad[(k4+1)*AD_S + 2*rr] = dup2(va.y);
        *(ull*)&Ad[(k4+2)*AD_S + 2*rr] = dup2(va.z);
        *(ull*)&Ad[(k4+3)*AD_S + 2*rr] = dup2(va.w);
        float4 vb = *(const float4*)&Z[(size_t)(cbase + rr) * Z_DIM + k4];
        Bp[(k4+0)*BP_S + rr] = vb.x;
        Bp[(k4+1)*BP_S + rr] = vb.y;
        Bp[(k4+2)*BP_S + rr] = vb.z;
        Bp[(k4+3)*BP_S + rr] = vb.w;
    }
    __syncthreads();

    ull acc[8][4] = {};
    const int ra = ty * 8;
    const int cb = tx * 8;

    #pragma unroll 2
    for (int k = 0; k < Z_DIM; ++k) {
        const ulonglong2* ap = (const ulonglong2*)&Ad[k * AD_S + 2 * ra];
        const ulonglong2* bp = (const ulonglong2*)&Bp[k * BP_S + cb];
        ulonglong2 a01 = ap[0], a23 = ap[1], a45 = ap[2], a67 = ap[3];
        ulonglong2 b01 = bp[0], b23 = bp[1];
        ull a[8] = { a01.x, a01.y, a23.x, a23.y, a45.x, a45.y, a67.x, a67.y };
        ull b[4] = { b01.x, b01.y, b23.x, b23.y };
        #pragma unroll
        for (int i = 0; i < 8; ++i) {
            #pragma unroll
            for (int jp = 0; jp < 4; ++jp)
                acc[i][jp] = fma2(a[i], b[jp], acc[i][jp]);
        }
    }

    // direct (lower-triangle) tile: stream 8 floats per row, never 64 live
    #pragma unroll
    for (int i = 0; i < 8; ++i) {
        float2 v0 = unpack2(acc[i][0]);
        float2 v1 = unpack2(acc[i][1]);
        float2 v2 = unpack2(acc[i][2]);
        float2 v3 = unpack2(acc[i][3]);
        size_t off = (size_t)(rbase + ra + i) * N_NODES + cbase + cb;
        *(float4*)&C[off]     = make_float4(v0.x, v0.y, v1.x, v1.y);
        *(float4*)&C[off + 4] = make_float4(v2.x, v2.y, v3.x, v3.y);
    }

    if (bx == by) return;

    // mirror via swizzled smem transpose bounce; re-unpack from acc (cheap
    // movs) instead of keeping av[64] live.
    __syncthreads();
    float* T = sm;   // 128 * 132 floats, fits the staging footprint
    #pragma unroll
    for (int i = 0; i < 8; ++i) {
        int b = ra + i;
        #pragma unroll
        for (int jp = 0; jp < 4; ++jp) {
            float2 v = unpack2(acc[i][jp]);
            int a0 = cb + 2*jp;
            int a1 = a0 + 1;
            T[a0 * ZLD + ((b + (a0 & 120)) & 127)] = v.x;
            T[a1 * ZLD + ((b + (a1 & 120)) & 127)] = v.y;
        }
    }
    __syncthreads();

    #pragma unroll
    for (int i = 0; i < 8; ++i) {
        int a = ty * 8 + i;
        int rot = a & 120;
        float4 v0 = *(const float4*)&T[a * ZLD + ((tx * 8     + rot) & 127)];
        float4 v1 = *(const float4*)&T[a * ZLD + ((tx * 8 + 4 + rot) & 127)];
        size_t off = (size_t)(cbase + a) * N_NODES + rbase + tx * 8;
        *(float4*)&C[off]     = v0;
        *(float4*)&C[off + 4] = v1;
    }
}

// ---------------------------------------------------------------------------
extern "C" void kernel_launch(void* const* d_in, const int* in_sizes, int n_in,
                              void* d_out, int out_size)
{
    const float* x    = (const float*)d_in[0];
    const float* w1   = (const float*)d_in[1];
    const float* w2   = (const float*)d_in[2];
    const int*   erow = (const int*)  d_in[3];
    const int*   ecol = (const int*)  d_in[4];
    const float* ew   = (const float*)d_in[5];

    float* out   = (float*)d_out;
    float* recon = out;                                   // [N, N]
    float* z     = out + (size_t)N_NODES * N_NODES;       // [N, Z_DIM]

    float *h0, *h, *p;
    cudaGetSymbolAddress((void**)&h0, g_h0);
    cudaGetSymbolAddress((void**)&h,  g_h);
    cudaGetSymbolAddress((void**)&p,  g_p);

    // 1. CSR row pointers
    rowptr_kernel<<<(N_NODES + 256) / 256, 256>>>(erow);

    // 2. h0 = x @ W1  [8192 x 256]
    dim3 g1(HID_DIM / 64, N_NODES / 64);
    sgemm_nn<64, 64, 16, 256><<<g1, 256>>>(x, w1, h0, N_NODES, IN_DIM, HID_DIM);

    // 3. h = relu(spmm(h0))
    spmm_kernel<HID_DIM, true><<<N_NODES / 4, dim3(HID_DIM / 4, 4)>>>(h0, ecol, ew, h);

    // 4. p = h @ W2  [8192 x 64]
    dim3 g2(Z_DIM / 64, N_NODES / 64);
    sgemm_nn<64, 64, 16, 256><<<g2, 256>>>(h, w2, p, N_NODES, HID_DIM, Z_DIM);

    // 5. z = spmm(p) -> output tail
    spmm_kernel<Z_DIM, false><<<N_NODES / 16, dim3(Z_DIM / 4, 16)>>>(p, ecol, ew, z);

    // 6. recon = z @ z^T, symmetric lower-triangle grid
    const int n_tiles = N_NODES / ZT;                       // 64
    const int n_blocks = n_tiles * (n_tiles + 1) / 2;       // 2080
    const int zzt_smem = (Z_DIM * AD_S + Z_DIM * BP_S) * (int)sizeof(float); // 102400
    cudaFuncSetAttribute(zzt_sym_kernel, cudaFuncAttributeMaxDynamicSharedMemorySize, zzt_smem);
    zzt_sym_kernel<<<n_blocks, 256, zzt_smem>>>(z, recon);
}

// round 5
// speedup vs baseline: 1.7842x; 1.7842x over previous
#include <cuda_runtime.h>
#include <cstdint>

#define N_NODES 8192
#define E_EDGES 262144
#define IN_DIM  512
#define HID_DIM 256
#define Z_DIM   64

typedef unsigned long long ull;

// Scratch (device globals: allocation-free)
__device__ float g_h0[N_NODES * HID_DIM];   // x @ W1
__device__ float g_h [N_NODES * HID_DIM];   // relu(spmm(h0))
__device__ float g_p [N_NODES * Z_DIM];     // h @ W2
__device__ int   g_rowptr[N_NODES + 1];

// ---------------------------------------------------------------------------
// Packed f32x2 helpers (kept for the dense GEMMs, which measured fine)
// ---------------------------------------------------------------------------
__device__ __forceinline__ ull pack2(float x, float y) {
    ull r; asm("mov.b64 %0, {%1, %2};" : "=l"(r) : "f"(x), "f"(y)); return r;
}
__device__ __forceinline__ ull dup2(float x) { return pack2(x, x); }
__device__ __forceinline__ ull fma2(ull a, ull b, ull c) {
    ull d; asm("fma.rn.f32x2 %0, %1, %2, %3;" : "=l"(d) : "l"(a), "l"(b), "l"(c));
    return d;
}
__device__ __forceinline__ float2 unpack2(ull v) {
    float2 f; asm("mov.b64 {%0, %1}, %2;" : "=f"(f.x), "=f"(f.y) : "l"(v)); return f;
}

// ---------------------------------------------------------------------------
// CSR row pointer from sorted edge_row
// ---------------------------------------------------------------------------
__global__ void rowptr_kernel(const int* __restrict__ er) {
    int i = blockIdx.x * blockDim.x + threadIdx.x;
    if (i > N_NODES) return;
    int lo = 0, hi = E_EDGES;
    while (lo < hi) {
        int mid = (lo + hi) >> 1;
        if (er[mid] < i) lo = mid + 1; else hi = mid;
    }
    g_rowptr[i] = lo;
}

// ---------------------------------------------------------------------------
// Tiled fp32 GEMM, register-prefetch double buffering (unchanged, measured OK)
// ---------------------------------------------------------------------------
template<int BM, int BN, int BK, int NT>
__global__ __launch_bounds__(NT) void sgemm_nn(
    const float* __restrict__ A, const float* __restrict__ B,
    float* __restrict__ C, int M, int K, int N)
{
    __shared__ float As[BK][BM + 4];
    __shared__ float Bs[BK][BN];
    const int LA = BM * BK / NT;
    const int LB = BK * BN / NT;
    const int tid = threadIdx.x;
    const int tx = tid % (BN / 4);
    const int ty = tid / (BN / 4);
    const int mbase = blockIdx.y * BM;
    const int nbase = blockIdx.x * BN;

    ull acc[4][2] = {};
    float apf[LA], bpf[LB];

    #pragma unroll
    for (int u = 0; u < LA; ++u) {
        int idx = tid + u * NT; int m = idx / BK, k = idx % BK;
        apf[u] = A[(size_t)(mbase + m) * K + k];
    }
    #pragma unroll
    for (int u = 0; u < LB; ++u) {
        int idx = tid + u * NT; int k = idx / BN, n = idx % BN;
        bpf[u] = B[(size_t)k * N + nbase + n];
    }

    for (int kk = 0; kk < K; kk += BK) {
        #pragma unroll
        for (int u = 0; u < LA; ++u) {
            int idx = tid + u * NT; int m = idx / BK, k = idx % BK;
            As[k][m] = apf[u];
        }
        #pragma unroll
        for (int u = 0; u < LB; ++u) {
            int idx = tid + u * NT; int k = idx / BN, n = idx % BN;
            Bs[k][n] = bpf[u];
        }
        __syncthreads();

        if (kk + BK < K) {
            #pragma unroll
            for (int u = 0; u < LA; ++u) {
                int idx = tid + u * NT; int m = idx / BK, k = idx % BK;
                apf[u] = A[(size_t)(mbase + m) * K + kk + BK + k];
            }
            #pragma unroll
            for (int u = 0; u < LB; ++u) {
                int idx = tid + u * NT; int k = idx / BN, n = idx % BN;
                bpf[u] = B[(size_t)(kk + BK + k) * N + nbase + n];
            }
        }

        #pragma unroll
        for (int k = 0; k < BK; ++k) {
            float4 a4 = *(const float4*)&As[k][ty * 4];
            float4 b4 = *(const float4*)&Bs[k][tx * 4];
            ull b2[2] = { pack2(b4.x, b4.y), pack2(b4.z, b4.w) };
            float a[4] = { a4.x, a4.y, a4.z, a4.w };
            #pragma unroll
            for (int i = 0; i < 4; ++i) {
                ull ad = dup2(a[i]);
                acc[i][0] = fma2(ad, b2[0], acc[i][0]);
                acc[i][1] = fma2(ad, b2[1], acc[i][1]);
            }
        }
        __syncthreads();
    }

    #pragma unroll
    for (int i = 0; i < 4; ++i) {
        float2 c0 = unpack2(acc[i][0]);
        float2 c1 = unpack2(acc[i][1]);
        size_t off = (size_t)(mbase + ty * 4 + i) * N + nbase + tx * 4;
        *(float4*)&C[off] = make_float4(c0.x, c0.y, c1.x, c1.y);
    }
}

// ---------------------------------------------------------------------------
// SpMM, float4 lanes (unchanged)
// ---------------------------------------------------------------------------
template<int D, bool RELU>
__global__ void spmm_kernel(const float* __restrict__ hin,
                            const int*   __restrict__ col,
                            const float* __restrict__ wgt,
                            float* __restrict__ hout)
{
    int row = blockIdx.x * blockDim.y + threadIdx.y;
    int d4 = threadIdx.x * 4;
    int s = g_rowptr[row];
    int e = g_rowptr[row + 1];
    float ax = 0.f, ay = 0.f, az = 0.f, aw = 0.f;
    int i = s;
    for (; i + 4 <= e; i += 4) {
        int   c0 = col[i+0], c1 = col[i+1], c2 = col[i+2], c3 = col[i+3];
        float w0 = wgt[i+0], w1 = wgt[i+1], w2 = wgt[i+2], w3 = wgt[i+3];
        float4 v0 = *(const float4*)&hin[(size_t)c0 * D + d4];
        float4 v1 = *(const float4*)&hin[(size_t)c1 * D + d4];
        float4 v2 = *(const float4*)&hin[(size_t)c2 * D + d4];
        float4 v3 = *(const float4*)&hin[(size_t)c3 * D + d4];
        ax += w0*v0.x + w1*v1.x + w2*v2.x + w3*v3.x;
        ay += w0*v0.y + w1*v1.y + w2*v2.y + w3*v3.y;
        az += w0*v0.z + w1*v1.z + w2*v2.z + w3*v3.z;
        aw += w0*v0.w + w1*v1.w + w2*v2.w + w3*v3.w;
    }
    for (; i < e; ++i) {
        float w = wgt[i];
        float4 v = *(const float4*)&hin[(size_t)col[i] * D + d4];
        ax += w*v.x; ay += w*v.y; az += w*v.z; aw += w*v.w;
    }
    if (RELU) {
        ax = fmaxf(ax, 0.f); ay = fmaxf(ay, 0.f);
        az = fmaxf(az, 0.f); aw = fmaxf(aw, 0.f);
    }
    *(float4*)&hout[(size_t)row * D + d4] = make_float4(ax, ay, az, aw);
}

// ---------------------------------------------------------------------------
// recon = Z @ Z^T via tf32 tensor cores (mma.sync.m16n8k8).
// 128x128 tile/block, 8 warps (2x4), warp tile 64x32, K=64 fully staged.
// Lower-triangle grid; mirror tile via swizzled smem transpose bounce.
// ---------------------------------------------------------------------------
#define ZT     128
#define TS     68    // smem stride (floats): (r*68+c)%32 spreads banks
#define ZLD    132   // mirror-bounce stride

__device__ __forceinline__ uint32_t f2tf32(float f) {
    uint32_t r; asm("cvt.rna.tf32.f32 %0, %1;" : "=r"(r) : "f"(f)); return r;
}

__device__ __forceinline__ void mma_tf32(float d[4],
    uint32_t a0, uint32_t a1, uint32_t a2, uint32_t a3,
    uint32_t b0, uint32_t b1)
{
    asm("mma.sync.aligned.m16n8k8.row.col.f32.tf32.tf32.f32 "
        "{%0,%1,%2,%3}, {%4,%5,%6,%7}, {%8,%9}, {%0,%1,%2,%3};"
        : "+f"(d[0]), "+f"(d[1]), "+f"(d[2]), "+f"(d[3])
        : "r"(a0), "r"(a1), "r"(a2), "r"(a3), "r"(b0), "r"(b1));
}

__global__ __launch_bounds__(256) void zzt_tc_kernel(
    const float* __restrict__ Z, float* __restrict__ C)
{
    extern __shared__ uint32_t smu[];
    uint32_t* As = smu;                 // [128][TS] tf32 bits: As[r][k]=Z[rbase+r][k]
    uint32_t* Bs = smu + ZT * TS;       // [128][TS]:           Bs[c][k]=Z[cbase+c][k]

    // triangular index -> (bx, by), bx <= by
    const int l = blockIdx.x;
    int by = (int)((sqrtf(8.0f * (float)l + 1.0f) - 1.0f) * 0.5f);
    while ((by + 1) * (by + 2) / 2 <= l) ++by;
    while (by * (by + 1) / 2 > l) --by;
    const int bx = l - by * (by + 1) / 2;

    const int tid  = threadIdx.x;
    const int lane = tid & 31;
    const int warp = tid >> 5;
    const int gid  = lane >> 2;     // 0..7
    const int tig  = lane & 3;      // 0..3
    const int wm   = (warp & 1) * 64;
    const int wn   = (warp >> 1) * 32;
    const int rbase = by * ZT;
    const int cbase = bx * ZT;

    // stage both operand tiles (fp32 -> tf32 bits), 8 float4 per thread each
    #pragma unroll
    for (int u = 0; u < 8; ++u) {
        int idx = tid + u * 256;            // 0..2047
        int r = idx >> 4, c4 = (idx & 15) << 2;
        float4 va = *(const float4*)&Z[(size_t)(rbase + r) * Z_DIM + c4];
        uint4 ta = { f2tf32(va.x), f2tf32(va.y), f2tf32(va.z), f2tf32(va.w) };
        *(uint4*)&As[r * TS + c4] = ta;
        float4 vb = *(const float4*)&Z[(size_t)(cbase + r) * Z_DIM + c4];
        uint4 tb = { f2tf32(vb.x), f2tf32(vb.y), f2tf32(vb.z), f2tf32(vb.w) };
        *(uint4*)&Bs[r * TS + c4] = tb;
    }
    __syncthreads();

    float acc[4][4][4] = {};

    #pragma unroll
    for (int kb = 0; kb < 8; ++kb) {
        const int k0 = kb * 8;
        uint32_t a[4][4], b[4][2];
        #pragma unroll
        for (int mi = 0; mi < 4; ++mi) {
            int base = (wm + mi * 16 + gid) * TS + k0 + tig;
            a[mi][0] = As[base];
            a[mi][1] = As[base + 8 * TS];
            a[mi][2] = As[base + 4];
            a[mi][3] = As[base + 8 * TS + 4];
        }
        #pragma unroll
        for (int ni = 0; ni < 4; ++ni) {
            int base = (wn + ni * 8 + gid) * TS + k0 + tig;
            b[ni][0] = Bs[base];
            b[ni][1] = Bs[base + 4];
        }
        #pragma unroll
        for (int mi = 0; mi < 4; ++mi)
            #pragma unroll
            for (int ni = 0; ni < 4; ++ni)
                mma_tf32(acc[mi][ni], a[mi][0], a[mi][1], a[mi][2], a[mi][3],
                         b[ni][0], b[ni][1]);
    }

    // direct (lower-triangle) tile straight from fragments.
    // Each STG.64: 4 lanes x 8B contiguous = one full 32B sector per row.
    #pragma unroll
    for (int mi = 0; mi < 4; ++mi) {
        #pragma unroll
        for (int ni = 0; ni < 4; ++ni) {
            int c = cbase + wn + ni * 8 + 2 * tig;
            size_t r0 = (size_t)(rbase + wm + mi * 16 + gid) * N_NODES;
            size_t r1 = r0 + 8 * N_NODES;
            *(float2*)&C[r0 + c] = make_float2(acc[mi][ni][0], acc[mi][ni][1]);
            *(float2*)&C[r1 + c] = make_float2(acc[mi][ni][2], acc[mi][ni][3]);
        }
    }

    if (bx == by) return;

    // mirror tile: transpose through smem with rotation swizzle, then
    // coalesced float4 row writes.
    __syncthreads();
    float* T = (float*)smu;   // 128*132 floats = 67584 B <= staging footprint
    #pragma unroll
    for (int mi = 0; mi < 4; ++mi) {
        #pragma unroll
        for (int ni = 0; ni < 4; ++ni) {
            #pragma unroll
            for (int q = 0; q < 4; ++q) {
                int r = wm + mi * 16 + gid + (q >> 1) * 8;    // local row
                int c = wn + ni * 8 + 2 * tig + (q & 1);      // local col
                T[c * ZLD + ((r + (c & 120)) & 127)] = acc[mi][ni][q];
            }
        }
    }
    __syncthreads();

    const int a  = tid >> 1;            // mirror-tile local row (= orig col)
    const int hb = (tid & 1) * 64;      // half-row offset
    const int rot = a & 120;
    #pragma unroll
    for (int j = 0; j < 16; ++j) {
        int b = hb + j * 4;
        float4 v = *(const float4*)&T[a * ZLD + ((b + rot) & 127)];
        *(float4*)&C[(size_t)(cbase + a) * N_NODES + rbase + b] = v;
    }
}

// ---------------------------------------------------------------------------
extern "C" void kernel_launch(void* const* d_in, const int* in_sizes, int n_in,
                              void* d_out, int out_size)
{
    const float* x    = (const float*)d_in[0];
    const float* w1   = (const float*)d_in[1];
    const float* w2   = (const float*)d_in[2];
    const int*   erow = (const int*)  d_in[3];
    const int*   ecol = (const int*)  d_in[4];
    const float* ew   = (const float*)d_in[5];

    float* out   = (float*)d_out;
    float* recon = out;                                   // [N, N]
    float* z     = out + (size_t)N_NODES * N_NODES;       // [N, Z_DIM]

    float *h0, *h, *p;
    cudaGetSymbolAddress((void**)&h0, g_h0);
    cudaGetSymbolAddress((void**)&h,  g_h);
    cudaGetSymbolAddress((void**)&p,  g_p);

    // 1. CSR row pointers
    rowptr_kernel<<<(N_NODES + 256) / 256, 256>>>(erow);

    // 2. h0 = x @ W1  [8192 x 256]
    dim3 g1(HID_DIM / 64, N_NODES / 64);
    sgemm_nn<64, 64, 16, 256><<<g1, 256>>>(x, w1, h0, N_NODES, IN_DIM, HID_DIM);

    // 3. h = relu(spmm(h0))
    spmm_kernel<HID_DIM, true><<<N_NODES / 4, dim3(HID_DIM / 4, 4)>>>(h0, ecol, ew, h);

    // 4. p = h @ W2  [8192 x 64]
    dim3 g2(Z_DIM / 64, N_NODES / 64);
    sgemm_nn<64, 64, 16, 256><<<g2, 256>>>(h, w2, p, N_NODES, HID_DIM, Z_DIM);

    // 5. z = spmm(p) -> output tail
    spmm_kernel<Z_DIM, false><<<N_NODES / 16, dim3(Z_DIM / 4, 16)>>>(p, ecol, ew, z);

    // 6. recon = z @ z^T, tf32 tensor cores, symmetric lower-triangle grid
    const int n_tiles = N_NODES / ZT;                       // 64
    const int n_blocks = n_tiles * (n_tiles + 1) / 2;       // 2080
    const int zzt_smem = 2 * ZT * TS * (int)sizeof(uint32_t);   // 69632 B
    cudaFuncSetAttribute(zzt_tc_kernel, cudaFuncAttributeMaxDynamicSharedMemorySize, zzt_smem);
    zzt_tc_kernel<<<n_blocks, 256, zzt_smem>>>(z, recon);
}

// round 6
// speedup vs baseline: 2.0974x; 1.1756x over previous
#include <cuda_runtime.h>
#include <cstdint>

#define N_NODES 8192
#define E_EDGES 262144
#define IN_DIM  512
#define HID_DIM 256
#define Z_DIM   64

// Scratch (device globals: allocation-free)
__device__ float g_h0[N_NODES * HID_DIM];   // x @ W1
__device__ float g_h [N_NODES * HID_DIM];   // relu(spmm(h0))
__device__ float g_p [N_NODES * Z_DIM];     // h @ W2
__device__ int   g_rowptr[N_NODES + 1];

// ---------------------------------------------------------------------------
// tf32 helpers
// ---------------------------------------------------------------------------
__device__ __forceinline__ uint32_t f2tf32(float f) {
    uint32_t r; asm("cvt.rna.tf32.f32 %0, %1;" : "=r"(r) : "f"(f)); return r;
}

__device__ __forceinline__ void mma_tf32(float d[4],
    uint32_t a0, uint32_t a1, uint32_t a2, uint32_t a3,
    uint32_t b0, uint32_t b1)
{
    asm("mma.sync.aligned.m16n8k8.row.col.f32.tf32.tf32.f32 "
        "{%0,%1,%2,%3}, {%4,%5,%6,%7}, {%8,%9}, {%0,%1,%2,%3};"
        : "+f"(d[0]), "+f"(d[1]), "+f"(d[2]), "+f"(d[3])
        : "r"(a0), "r"(a1), "r"(a2), "r"(a3), "r"(b0), "r"(b1));
}

// ---------------------------------------------------------------------------
// CSR row pointer from sorted edge_row
// ---------------------------------------------------------------------------
__global__ void rowptr_kernel(const int* __restrict__ er) {
    int i = blockIdx.x * blockDim.x + threadIdx.x;
    if (i > N_NODES) return;
    int lo = 0, hi = E_EDGES;
    while (lo < hi) {
        int mid = (lo + hi) >> 1;
        if (er[mid] < i) lo = mid + 1; else hi = mid;
    }
    g_rowptr[i] = lo;
}

// ---------------------------------------------------------------------------
// tf32 tensor-core GEMM: C[M,N] = A[M,K] @ B[K,N]  (fp32 in/out).
// 256 threads = 8 warps arranged (BM/WM) x (BN/WN); warp tile WM x WN.
// A staged row-major (m x k), B staged transposed (n x k); stride BK+4.
// Register-prefetch double buffering over K tiles of BK=32.
// ---------------------------------------------------------------------------
#define GS 36   // smem stride = BK + 4

template<int BM, int BN, int WM, int WN>
__global__ __launch_bounds__(256) void gemm_tc(
    const float* __restrict__ A, const float* __restrict__ B,
    float* __restrict__ C, int M, int K, int N)
{
    constexpr int BK = 32;
    constexpr int MI = WM / 16;
    constexpr int NI = WN / 8;
    constexpr int NWN = BN / WN;                 // warps along n
    constexpr int LA = BM * (BK / 4) / 256;      // float4 A loads / thread
    constexpr int LB = BK * (BN / 4) / 256;      // float4 B loads / thread

    extern __shared__ uint32_t gsm[];
    uint32_t* As = gsm;                  // [BM][GS]
    uint32_t* Bs = gsm + BM * GS;        // [BN][GS]  (n-major)

    const int tid  = threadIdx.x;
    const int lane = tid & 31;
    const int warp = tid >> 5;
    const int gid  = lane >> 2;
    const int tig  = lane & 3;
    const int wm   = (warp / NWN) * WM;
    const int wn   = (warp % NWN) * WN;
    const int mbase = blockIdx.y * BM;
    const int nbase = blockIdx.x * BN;

    float acc[MI][NI][4] = {};
    float4 apf[LA], bpf[LB];

    // prefetch k-tile 0
    #pragma unroll
    for (int u = 0; u < LA; ++u) {
        int idx = tid + u * 256;
        int r = idx / (BK / 4), c4 = (idx % (BK / 4)) * 4;
        apf[u] = *(const float4*)&A[(size_t)(mbase + r) * K + c4];
    }
    #pragma unroll
    for (int u = 0; u < LB; ++u) {
        int idx = tid + u * 256;
        int k = idx / (BN / 4), n4 = (idx % (BN / 4)) * 4;
        bpf[u] = *(const float4*)&B[(size_t)k * N + nbase + n4];
    }

    for (int kk = 0; kk < K; kk += BK) {
        // store staged tiles (fp32 -> tf32 bits)
        #pragma unroll
        for (int u = 0; u < LA; ++u) {
            int idx = tid + u * 256;
            int r = idx / (BK / 4), c4 = (idx % (BK / 4)) * 4;
            uint4 t = { f2tf32(apf[u].x), f2tf32(apf[u].y),
                        f2tf32(apf[u].z), f2tf32(apf[u].w) };
            *(uint4*)&As[r * GS + c4] = t;
        }
        #pragma unroll
        for (int u = 0; u < LB; ++u) {
            int idx = tid + u * 256;
            int k = idx / (BN / 4), n4 = (idx % (BN / 4)) * 4;
            Bs[(n4 + 0) * GS + k] = f2tf32(bpf[u].x);
            Bs[(n4 + 1) * GS + k] = f2tf32(bpf[u].y);
            Bs[(n4 + 2) * GS + k] = f2tf32(bpf[u].z);
            Bs[(n4 + 3) * GS + k] = f2tf32(bpf[u].w);
        }
        __syncthreads();

        // prefetch next k-tile
        if (kk + BK < K) {
            #pragma unroll
            for (int u = 0; u < LA; ++u) {
                int idx = tid + u * 256;
                int r = idx / (BK / 4), c4 = (idx % (BK / 4)) * 4;
                apf[u] = *(const float4*)&A[(size_t)(mbase + r) * K + kk + BK + c4];
            }
            #pragma unroll
            for (int u = 0; u < LB; ++u) {
                int idx = tid + u * 256;
                int k = idx / (BN / 4), n4 = (idx % (BN / 4)) * 4;
                bpf[u] = *(const float4*)&B[(size_t)(kk + BK + k) * N + nbase + n4];
            }
        }

        // compute: 4 k-groups of 8
        #pragma unroll
        for (int kb = 0; kb < 4; ++kb) {
            const int kc = kb * 8;
            uint32_t a[MI][4], b[NI][2];
            #pragma unroll
            for (int mi = 0; mi < MI; ++mi) {
                int base = (wm + mi * 16 + gid) * GS + kc + tig;
                a[mi][0] = As[base];
                a[mi][1] = As[base + 8 * GS];
                a[mi][2] = As[base + 4];
                a[mi][3] = As[base + 8 * GS + 4];
            }
            #pragma unroll
            for (int ni = 0; ni < NI; ++ni) {
                int base = (wn + ni * 8 + gid) * GS + kc + tig;
                b[ni][0] = Bs[base];
                b[ni][1] = Bs[base + 4];
            }
            #pragma unroll
            for (int mi = 0; mi < MI; ++mi)
                #pragma unroll
                for (int ni = 0; ni < NI; ++ni)
                    mma_tf32(acc[mi][ni], a[mi][0], a[mi][1], a[mi][2], a[mi][3],
                             b[ni][0], b[ni][1]);
        }
        __syncthreads();
    }

    // epilogue: write fragments (fp32)
    #pragma unroll
    for (int mi = 0; mi < MI; ++mi) {
        #pragma unroll
        for (int ni = 0; ni < NI; ++ni) {
            int col = nbase + wn + ni * 8 + 2 * tig;
            size_t r0 = (size_t)(mbase + wm + mi * 16 + gid) * N;
            size_t r1 = r0 + 8 * (size_t)N;
            *(float2*)&C[r0 + col] = make_float2(acc[mi][ni][0], acc[mi][ni][1]);
            *(float2*)&C[r1 + col] = make_float2(acc[mi][ni][2], acc[mi][ni][3]);
        }
    }
}

// ---------------------------------------------------------------------------
// SpMM, float4 lanes (unchanged)
// ---------------------------------------------------------------------------
template<int D, bool RELU>
__global__ void spmm_kernel(const float* __restrict__ hin,
                            const int*   __restrict__ col,
                            const float* __restrict__ wgt,
                            float* __restrict__ hout)
{
    int row = blockIdx.x * blockDim.y + threadIdx.y;
    int d4 = threadIdx.x * 4;
    int s = g_rowptr[row];
    int e = g_rowptr[row + 1];
    float ax = 0.f, ay = 0.f, az = 0.f, aw = 0.f;
    int i = s;
    for (; i + 4 <= e; i += 4) {
        int   c0 = col[i+0], c1 = col[i+1], c2 = col[i+2], c3 = col[i+3];
        float w0 = wgt[i+0], w1 = wgt[i+1], w2 = wgt[i+2], w3 = wgt[i+3];
        float4 v0 = *(const float4*)&hin[(size_t)c0 * D + d4];
        float4 v1 = *(const float4*)&hin[(size_t)c1 * D + d4];
        float4 v2 = *(const float4*)&hin[(size_t)c2 * D + d4];
        float4 v3 = *(const float4*)&hin[(size_t)c3 * D + d4];
        ax += w0*v0.x + w1*v1.x + w2*v2.x + w3*v3.x;
        ay += w0*v0.y + w1*v1.y + w2*v2.y + w3*v3.y;
        az += w0*v0.z + w1*v1.z + w2*v2.z + w3*v3.z;
        aw += w0*v0.w + w1*v1.w + w2*v2.w + w3*v3.w;
    }
    for (; i < e; ++i) {
        float w = wgt[i];
        float4 v = *(const float4*)&hin[(size_t)col[i] * D + d4];
        ax += w*v.x; ay += w*v.y; az += w*v.z; aw += w*v.w;
    }
    if (RELU) {
        ax = fmaxf(ax, 0.f); ay = fmaxf(ay, 0.f);
        az = fmaxf(az, 0.f); aw = fmaxf(aw, 0.f);
    }
    *(float4*)&hout[(size_t)row * D + d4] = make_float4(ax, ay, az, aw);
}

// ---------------------------------------------------------------------------
// recon = Z @ Z^T via tf32 tensor cores (unchanged from R5 — it works).
// ---------------------------------------------------------------------------
#define ZT     128
#define TS     68
#define ZLD    132

__global__ __launch_bounds__(256) void zzt_tc_kernel(
    const float* __restrict__ Z, float* __restrict__ C)
{
    extern __shared__ uint32_t smu[];
    uint32_t* As = smu;
    uint32_t* Bs = smu + ZT * TS;

    const int l = blockIdx.x;
    int by = (int)((sqrtf(8.0f * (float)l + 1.0f) - 1.0f) * 0.5f);
    while ((by + 1) * (by + 2) / 2 <= l) ++by;
    while (by * (by + 1) / 2 > l) --by;
    const int bx = l - by * (by + 1) / 2;

    const int tid  = threadIdx.x;
    const int lane = tid & 31;
    const int warp = tid >> 5;
    const int gid  = lane >> 2;
    const int tig  = lane & 3;
    const int wm   = (warp & 1) * 64;
    const int wn   = (warp >> 1) * 32;
    const int rbase = by * ZT;
    const int cbase = bx * ZT;

    #pragma unroll
    for (int u = 0; u < 8; ++u) {
        int idx = tid + u * 256;
        int r = idx >> 4, c4 = (idx & 15) << 2;
        float4 va = *(const float4*)&Z[(size_t)(rbase + r) * Z_DIM + c4];
        uint4 ta = { f2tf32(va.x), f2tf32(va.y), f2tf32(va.z), f2tf32(va.w) };
        *(uint4*)&As[r * TS + c4] = ta;
        float4 vb = *(const float4*)&Z[(size_t)(cbase + r) * Z_DIM + c4];
        uint4 tb = { f2tf32(vb.x), f2tf32(vb.y), f2tf32(vb.z), f2tf32(vb.w) };
        *(uint4*)&Bs[r * TS + c4] = tb;
    }
    __syncthreads();

    float acc[4][4][4] = {};

    #pragma unroll
    for (int kb = 0; kb < 8; ++kb) {
        const int k0 = kb * 8;
        uint32_t a[4][4], b[4][2];
        #pragma unroll
        for (int mi = 0; mi < 4; ++mi) {
            int base = (wm + mi * 16 + gid) * TS + k0 + tig;
            a[mi][0] = As[base];
            a[mi][1] = As[base + 8 * TS];
            a[mi][2] = As[base + 4];
            a[mi][3] = As[base + 8 * TS + 4];
        }
        #pragma unroll
        for (int ni = 0; ni < 4; ++ni) {
            int base = (wn + ni * 8 + gid) * TS + k0 + tig;
            b[ni][0] = Bs[base];
            b[ni][1] = Bs[base + 4];
        }
        #pragma unroll
        for (int mi = 0; mi < 4; ++mi)
            #pragma unroll
            for (int ni = 0; ni < 4; ++ni)
                mma_tf32(acc[mi][ni], a[mi][0], a[mi][1], a[mi][2], a[mi][3],
                         b[ni][0], b[ni][1]);
    }

    #pragma unroll
    for (int mi = 0; mi < 4; ++mi) {
        #pragma unroll
        for (int ni = 0; ni < 4; ++ni) {
            int c = cbase + wn + ni * 8 + 2 * tig;
            size_t r0 = (size_t)(rbase + wm + mi * 16 + gid) * N_NODES;
            size_t r1 = r0 + 8 * N_NODES;
            *(float2*)&C[r0 + c] = make_float2(acc[mi][ni][0], acc[mi][ni][1]);
            *(float2*)&C[r1 + c] = make_float2(acc[mi][ni][2], acc[mi][ni][3]);
        }
    }

    if (bx == by) return;

    __syncthreads();
    float* T = (float*)smu;
    #pragma unroll
    for (int mi = 0; mi < 4; ++mi) {
        #pragma unroll
        for (int ni = 0; ni < 4; ++ni) {
            #pragma unroll
            for (int q = 0; q < 4; ++q) {
                int r = wm + mi * 16 + gid + (q >> 1) * 8;
                int c = wn + ni * 8 + 2 * tig + (q & 1);
                T[c * ZLD + ((r + (c & 120)) & 127)] = acc[mi][ni][q];
            }
        }
    }
    __syncthreads();

    const int a  = tid >> 1;
    const int hb = (tid & 1) * 64;
    const int rot = a & 120;
    #pragma unroll
    for (int j = 0; j < 16; ++j) {
        int b = hb + j * 4;
        float4 v = *(const float4*)&T[a * ZLD + ((b + rot) & 127)];
        *(float4*)&C[(size_t)(cbase + a) * N_NODES + rbase + b] = v;
    }
}

// ---------------------------------------------------------------------------
extern "C" void kernel_launch(void* const* d_in, const int* in_sizes, int n_in,
                              void* d_out, int out_size)
{
    const float* x    = (const float*)d_in[0];
    const float* w1   = (const float*)d_in[1];
    const float* w2   = (const float*)d_in[2];
    const int*   erow = (const int*)  d_in[3];
    const int*   ecol = (const int*)  d_in[4];
    const float* ew   = (const float*)d_in[5];

    float* out   = (float*)d_out;
    float* recon = out;                                   // [N, N]
    float* z     = out + (size_t)N_NODES * N_NODES;       // [N, Z_DIM]

    float *h0, *h, *p;
    cudaGetSymbolAddress((void**)&h0, g_h0);
    cudaGetSymbolAddress((void**)&h,  g_h);
    cudaGetSymbolAddress((void**)&p,  g_p);

    // 1. CSR row pointers
    rowptr_kernel<<<(N_NODES + 256) / 256, 256>>>(erow);

    // 2. h0 = x @ W1  [8192 x 256] — tf32 TC, BM=128 BN=128 (warp 64x32)
    {
        const int smem = (128 + 128) * GS * (int)sizeof(uint32_t);   // 36864
        dim3 g(HID_DIM / 128, N_NODES / 128);                        // (2, 64)
        gemm_tc<128, 128, 64, 32><<<g, 256, smem>>>(x, w1, h0, N_NODES, IN_DIM, HID_DIM);
    }

    // 3. h = relu(spmm(h0))
    spmm_kernel<HID_DIM, true><<<N_NODES / 4, dim3(HID_DIM / 4, 4)>>>(h0, ecol, ew, h);

    // 4. p = h @ W2  [8192 x 64] — tf32 TC, BM=128 BN=64 (warp 32x32)
    {
        const int smem = (128 + 64) * GS * (int)sizeof(uint32_t);    // 27648
        dim3 g(Z_DIM / 64, N_NODES / 128);                           // (1, 64)
        gemm_tc<128, 64, 32, 32><<<g, 256, smem>>>(h, w2, p, N_NODES, HID_DIM, Z_DIM);
    }

    // 5. z = spmm(p) -> output tail
    spmm_kernel<Z_DIM, false><<<N_NODES / 16, dim3(Z_DIM / 4, 16)>>>(p, ecol, ew, z);

    // 6. recon = z @ z^T, tf32 tensor cores, symmetric lower-triangle grid
    const int n_tiles = N_NODES / ZT;                       // 64
    const int n_blocks = n_tiles * (n_tiles + 1) / 2;       // 2080
    const int zzt_smem = 2 * ZT * TS * (int)sizeof(uint32_t);   // 69632 B
    cudaFuncSetAttribute(zzt_tc_kernel, cudaFuncAttributeMaxDynamicSharedMemorySize, zzt_smem);
    zzt_tc_kernel<<<n_blocks, 256, zzt_smem>>>(z, recon);
}